// round 2
// baseline (speedup 1.0000x reference)
#include <cuda_runtime.h>
#include <math.h>

#define BATCH    4
#define SEQLEN   2048
#define DMODEL   1024
#define DSTATE   64
#define DCONV    4
#define HEADDIM  64
#define DINNER   2048
#define NH       32
#define CONVDIM  2176            // DINNER + 2*DSTATE
#define NPROJ    4256            // 2*DINNER + 2*DSTATE + NH
#define MROWS    (BATCH*SEQLEN)  // 8192

// ---------------- scratch (device globals; no allocation allowed) ----------
__device__ float g_zxbcdt[(size_t)MROWS * NPROJ];   // 139.5 MB
__device__ float g_xbc  [(size_t)MROWS * CONVDIM];  // 71.3 MB
__device__ float g_dt   [(size_t)MROWS * NH];
__device__ float g_y    [(size_t)MROWS * DINNER];   // 67 MB

// ---------------- generic fp32 tiled GEMM: C[M,N] = A[M,K] @ B[K,N] --------
// 64x64 tile, K-tile 16, 256 threads, 4x4 accum per thread.
// Assumes M % 64 == 0 and K % 16 == 0 (true for all calls); guards N edge.
__global__ __launch_bounds__(256) void gemm_kernel(
    const float* __restrict__ A, const float* __restrict__ B,
    float* __restrict__ C, int M, int N, int K)
{
    __shared__ float As[16][68];   // stored transposed: As[k][m]
    __shared__ float Bs[16][68];   // Bs[k][n]

    const int tid = threadIdx.x;
    const int tx  = tid & 15;      // col group
    const int ty  = tid >> 4;      // row group
    const int rowBase = blockIdx.y * 64;
    const int colBase = blockIdx.x * 64;

    // A-load mapping: thread loads A[rowBase+aR][k0+aK .. +3]
    const int aR = tid >> 2;          // 0..63
    const int aK = (tid & 3) * 4;     // 0,4,8,12
    // B-load mapping: thread loads B[k0+bK][colBase+bC .. +3]
    const int bK = tid >> 4;          // 0..15
    const int bC = (tid & 15) * 4;    // 0..60

    float acc[4][4];
    #pragma unroll
    for (int i = 0; i < 4; i++)
        #pragma unroll
        for (int j = 0; j < 4; j++) acc[i][j] = 0.f;

    const float* Aptr = A + (size_t)(rowBase + aR) * K + aK;
    const bool bOk = (colBase + bC) < N;

    for (int k0 = 0; k0 < K; k0 += 16) {
        float4 av = *(const float4*)(Aptr + k0);
        As[aK + 0][aR] = av.x;
        As[aK + 1][aR] = av.y;
        As[aK + 2][aR] = av.z;
        As[aK + 3][aR] = av.w;

        float4 bv = make_float4(0.f, 0.f, 0.f, 0.f);
        if (bOk) bv = *(const float4*)(B + (size_t)(k0 + bK) * N + colBase + bC);
        *(float4*)&Bs[bK][bC] = bv;

        __syncthreads();
        #pragma unroll
        for (int kk = 0; kk < 16; kk++) {
            float4 a4 = *(const float4*)&As[kk][ty * 4];
            float4 b4 = *(const float4*)&Bs[kk][tx * 4];
            float ar[4] = {a4.x, a4.y, a4.z, a4.w};
            float br[4] = {b4.x, b4.y, b4.z, b4.w};
            #pragma unroll
            for (int i = 0; i < 4; i++)
                #pragma unroll
                for (int j = 0; j < 4; j++)
                    acc[i][j] = fmaf(ar[i], br[j], acc[i][j]);
        }
        __syncthreads();
    }

    #pragma unroll
    for (int i = 0; i < 4; i++) {
        const int r = rowBase + ty * 4 + i;
        #pragma unroll
        for (int j = 0; j < 4; j++) {
            const int c = colBase + tx * 4 + j;
            if (c < N) C[(size_t)r * N + c] = acc[i][j];
        }
    }
}

// ---------------- causal depthwise conv1d (k=4) + bias + SiLU --------------
__global__ __launch_bounds__(256) void conv_kernel(
    const float* __restrict__ conv_w, const float* __restrict__ conv_b)
{
    const int l = blockIdx.x;
    const int b = blockIdx.y;
    const size_t orow = (size_t)(b * SEQLEN + l);

    for (int c = threadIdx.x; c < CONVDIM; c += 256) {
        float s = conv_b[c];
        #pragma unroll
        for (int k = 0; k < DCONV; k++) {
            const int ls = l - (DCONV - 1) + k;
            if (ls >= 0)
                s = fmaf(g_zxbcdt[((size_t)(b * SEQLEN + ls)) * NPROJ + DINNER + c],
                         conv_w[c * DCONV + k], s);
        }
        const float sil = s / (1.f + __expf(-s));
        g_xbc[orow * CONVDIM + c] = sil;
    }
}

// ---------------- dt = softplus(dt_raw + dt_bias) --------------------------
__global__ __launch_bounds__(256) void dt_kernel(const float* __restrict__ dt_bias)
{
    const int i = blockIdx.x * 256 + threadIdx.x;   // over MROWS*NH
    if (i >= MROWS * NH) return;
    const int h = i & (NH - 1);
    const int row = i >> 5;
    const float v = g_zxbcdt[(size_t)row * NPROJ + (DINNER + CONVDIM) + h] + dt_bias[h];
    g_dt[i] = (v > 20.f) ? v : log1pf(expf(v));
}

// ---------------- sequential selective scan --------------------------------
// Block = one (b, h). 256 threads: p = tid>>2 (0..63), n-chunk nc = tid&3
// (16 states each). 2-shuffle reduction over the 4 n-chunks per p.
// Distance-2 register prefetch of B/C/x/dt to hide L2 latency.
__global__ __launch_bounds__(256) void scan_kernel(
    const float* __restrict__ A_log, const float* __restrict__ Dv)
{
    const int bh = blockIdx.x;
    const int b = bh >> 5, h = bh & (NH - 1);
    const int tid = threadIdx.x;
    const int p  = tid >> 2;
    const int nc = tid & 3;
    const int n0 = nc * 16;

    const float Aneg = -__expf(A_log[h]);
    const float Dh   = Dv[h];

    const float* xptr = g_xbc + (size_t)b * SEQLEN * CONVDIM + h * HEADDIM + p;
    const float* Bptr = g_xbc + (size_t)b * SEQLEN * CONVDIM + DINNER + n0;
    const float* Cptr = g_xbc + (size_t)b * SEQLEN * CONVDIM + DINNER + DSTATE + n0;
    const float* dptr = g_dt  + (size_t)b * SEQLEN * NH + h;
    float*       yptr = g_y   + (size_t)b * SEQLEN * DINNER + h * HEADDIM + p;

    float hs[16];
    #pragma unroll
    for (int i = 0; i < 16; i++) hs[i] = 0.f;

    float4 Bf0[4], Cf0[4], Bf1[4], Cf1[4];
    float xf0, df0, xf1, df1;

#define SCAN_LOAD(t, Bf, Cf, xf, df) do {                                   \
        const float4* bp_ = (const float4*)(Bptr + (size_t)(t) * CONVDIM);  \
        Bf[0] = bp_[0]; Bf[1] = bp_[1]; Bf[2] = bp_[2]; Bf[3] = bp_[3];     \
        const float4* cp_ = (const float4*)(Cptr + (size_t)(t) * CONVDIM);  \
        Cf[0] = cp_[0]; Cf[1] = cp_[1]; Cf[2] = cp_[2]; Cf[3] = cp_[3];     \
        xf = xptr[(size_t)(t) * CONVDIM];                                   \
        df = dptr[(size_t)(t) * NH];                                        \
    } while (0)

#define SCAN_STEP(t, Bf, Cf, xf, df) do {                                   \
        const float dA   = __expf((df) * Aneg);                             \
        const float coef = (df) * (xf);                                     \
        float acc = 0.f;                                                    \
        _Pragma("unroll")                                                   \
        for (int q = 0; q < 4; q++) {                                       \
            const float4 bq = Bf[q], cq = Cf[q];                            \
            hs[q*4+0] = fmaf(hs[q*4+0], dA, coef * bq.x);                   \
            acc = fmaf(hs[q*4+0], cq.x, acc);                               \
            hs[q*4+1] = fmaf(hs[q*4+1], dA, coef * bq.y);                   \
            acc = fmaf(hs[q*4+1], cq.y, acc);                               \
            hs[q*4+2] = fmaf(hs[q*4+2], dA, coef * bq.z);                   \
            acc = fmaf(hs[q*4+2], cq.z, acc);                               \
            hs[q*4+3] = fmaf(hs[q*4+3], dA, coef * bq.w);                   \
            acc = fmaf(hs[q*4+3], cq.w, acc);                               \
        }                                                                   \
        acc += __shfl_xor_sync(0xffffffffu, acc, 1);                        \
        acc += __shfl_xor_sync(0xffffffffu, acc, 2);                        \
        if (nc == 0) yptr[(size_t)(t) * DINNER] = acc + Dh * (xf);          \
    } while (0)

    SCAN_LOAD(0, Bf0, Cf0, xf0, df0);
    SCAN_LOAD(1, Bf1, Cf1, xf1, df1);

    for (int t = 0; t < SEQLEN; t += 2) {
        SCAN_STEP(t, Bf0, Cf0, xf0, df0);
        if (t + 2 < SEQLEN) SCAN_LOAD(t + 2, Bf0, Cf0, xf0, df0);
        SCAN_STEP(t + 1, Bf1, Cf1, xf1, df1);
        if (t + 3 < SEQLEN) SCAN_LOAD(t + 3, Bf1, Cf1, xf1, df1);
    }
#undef SCAN_LOAD
#undef SCAN_STEP
}

// ---------------- y = rmsnorm(y * silu(z)) * norm_w (in place) -------------
__global__ __launch_bounds__(256) void gatenorm_kernel(const float* __restrict__ norm_w)
{
    const int row = blockIdx.x;
    const float* zrow = g_zxbcdt + (size_t)row * NPROJ;   // z = first DINNER cols
    float* yrow = g_y + (size_t)row * DINNER;

    float v[8];
    float ss = 0.f;
    #pragma unroll
    for (int j = 0; j < 8; j++) {
        const int i = threadIdx.x + j * 256;
        const float z = zrow[i];
        const float g = yrow[i] * (z / (1.f + __expf(-z)));
        v[j] = g;
        ss = fmaf(g, g, ss);
    }
    #pragma unroll
    for (int o = 16; o; o >>= 1) ss += __shfl_xor_sync(0xffffffffu, ss, o);

    __shared__ float red[8];
    __shared__ float s_rstd;
    if ((threadIdx.x & 31) == 0) red[threadIdx.x >> 5] = ss;
    __syncthreads();
    if (threadIdx.x == 0) {
        float t = 0.f;
        #pragma unroll
        for (int w = 0; w < 8; w++) t += red[w];
        s_rstd = rsqrtf(t / (float)DINNER + 1e-5f);
    }
    __syncthreads();
    const float rstd = s_rstd;

    #pragma unroll
    for (int j = 0; j < 8; j++) {
        const int i = threadIdx.x + j * 256;
        yrow[i] = v[j] * rstd * norm_w[i];
    }
}

// ---------------- launch ----------------------------------------------------
extern "C" void kernel_launch(void* const* d_in, const int* in_sizes, int n_in,
                              void* d_out, int out_size)
{
    const float* x       = (const float*)d_in[0];
    const float* W_in    = (const float*)d_in[1];
    const float* conv_w  = (const float*)d_in[2];
    const float* conv_b  = (const float*)d_in[3];
    const float* dt_bias = (const float*)d_in[4];
    const float* A_log   = (const float*)d_in[5];
    const float* Dvec    = (const float*)d_in[6];
    const float* norm_w  = (const float*)d_in[7];
    const float* W_out   = (const float*)d_in[8];
    float* out = (float*)d_out;

    void *p_zx, *p_y;
    cudaGetSymbolAddress(&p_zx, g_zxbcdt);
    cudaGetSymbolAddress(&p_y,  g_y);
    float* zx = (float*)p_zx;
    float* y  = (float*)p_y;

    // 1) in-projection: zxbcdt = x @ W_in   [8192,1024]@[1024,4256]
    {
        dim3 grid((NPROJ + 63) / 64, MROWS / 64);
        gemm_kernel<<<grid, 256>>>(x, W_in, zx, MROWS, NPROJ, DMODEL);
    }
    // 2) conv + SiLU
    conv_kernel<<<dim3(SEQLEN, BATCH), 256>>>(conv_w, conv_b);
    // 3) dt softplus
    dt_kernel<<<(MROWS * NH + 255) / 256, 256>>>(dt_bias);
    // 4) selective scan
    scan_kernel<<<BATCH * NH, 256>>>(A_log, Dvec);
    // 5) gate + rmsnorm (in place on g_y)
    gatenorm_kernel<<<MROWS, 256>>>(norm_w);
    // 6) out-projection: out = y @ W_out   [8192,2048]@[2048,1024]
    {
        dim3 grid(DMODEL / 64, MROWS / 64);
        gemm_kernel<<<grid, 256>>>(y, W_out, out, MROWS, DMODEL, DINNER);
    }
}

// round 4
// speedup vs baseline: 1.0980x; 1.0980x over previous
#include <cuda_runtime.h>
#include <math.h>

#define BATCH    4
#define SEQLEN   2048
#define DMODEL   1024
#define DSTATE   64
#define DCONV    4
#define HEADDIM  64
#define DINNER   2048
#define NH       32
#define CONVDIM  2176            // DINNER + 2*DSTATE
#define NPROJ    4256            // 2*DINNER + 2*DSTATE + NH
#define MROWS    (BATCH*SEQLEN)  // 8192

// ---------------- scratch (device globals; no allocation allowed) ----------
__device__ float g_zxbcdt[(size_t)MROWS * NPROJ];   // 139.5 MB
__device__ float g_xbc  [(size_t)MROWS * CONVDIM];  // 71.3 MB
__device__ float g_dt   [(size_t)MROWS * NH];
__device__ float g_y    [(size_t)MROWS * DINNER];   // 67 MB

// ---------------- packed f32x2 helpers (sm_103a FFMA2 path) ----------------
__device__ __forceinline__ unsigned long long pack2(float lo, float hi) {
    unsigned long long r;
    asm("mov.b64 %0, {%1, %2};" : "=l"(r) : "f"(lo), "f"(hi));
    return r;
}
__device__ __forceinline__ void ffma2(unsigned long long &d,
                                      unsigned long long a,
                                      unsigned long long b) {
    asm("fma.rn.f32x2 %0, %1, %2, %0;" : "+l"(d) : "l"(a), "l"(b));
}

// ---------------- fp32 GEMM via FFMA2: C[M,N] = A[M,K] @ B[K,N] ------------
// BM=BN=128, BK=16, 128 threads, 16x8 per thread (accum packed along M).
// Requires M%128==0, K%16==0, N%4==0 (true for all calls). N-edge guarded.
#define BM 128
#define BN 128
#define BK 16
#define LDS_PAD 4

__global__ __launch_bounds__(128) void gemm2_kernel(
    const float* __restrict__ A, const float* __restrict__ B,
    float* __restrict__ C, int M, int N, int K)
{
    __shared__ float As[2][BK][BM + LDS_PAD];   // transposed: As[k][m]
    __shared__ float Bs[2][BK][BN + LDS_PAD];   // Bs[k][n]

    const int tid = threadIdx.x;
    const int tx  = tid & 15;          // col group: 8 cols each
    const int ty  = tid >> 4;          // row group: 16 rows each
    const int rowBase = blockIdx.y * BM;
    const int colBase = blockIdx.x * BN;

    // A load: thread owns row (rowBase + tid), 16 k's per tile
    const float* Aptr = A + (size_t)(rowBase + tid) * K;
    // B load: bK = tid>>3 (0..15), 16 consecutive cols at bC
    const int bK = tid >> 3;
    const int bC = (tid & 7) * 16;

    unsigned long long acc[8][8];      // [m-pair][n]
    #pragma unroll
    for (int i = 0; i < 8; i++)
        #pragma unroll
        for (int j = 0; j < 8; j++) acc[i][j] = 0ULL;

    float4 aReg[4], bReg[4];

    // prologue: load tile 0 into regs, then smem buf 0
    #pragma unroll
    for (int f = 0; f < 4; f++)
        aReg[f] = *(const float4*)(Aptr + f * 4);
    #pragma unroll
    for (int f = 0; f < 4; f++) {
        const int col = colBase + bC + f * 4;
        bReg[f] = (col < N) ? *(const float4*)(B + (size_t)bK * N + col)
                            : make_float4(0.f, 0.f, 0.f, 0.f);
    }
    #pragma unroll
    for (int f = 0; f < 4; f++) {
        As[0][f * 4 + 0][tid] = aReg[f].x;
        As[0][f * 4 + 1][tid] = aReg[f].y;
        As[0][f * 4 + 2][tid] = aReg[f].z;
        As[0][f * 4 + 3][tid] = aReg[f].w;
        *(float4*)&Bs[0][bK][bC + f * 4] = bReg[f];
    }
    __syncthreads();

    int buf = 0;
    for (int k0 = 0; k0 < K; k0 += BK) {
        const bool more = (k0 + BK) < K;
        if (more) {
            #pragma unroll
            for (int f = 0; f < 4; f++)
                aReg[f] = *(const float4*)(Aptr + k0 + BK + f * 4);
            #pragma unroll
            for (int f = 0; f < 4; f++) {
                const int col = colBase + bC + f * 4;
                bReg[f] = (col < N)
                    ? *(const float4*)(B + (size_t)(k0 + BK + bK) * N + col)
                    : make_float4(0.f, 0.f, 0.f, 0.f);
            }
        }

        #pragma unroll
        for (int kk = 0; kk < BK; kk++) {
            float4 a0 = *(const float4*)&As[buf][kk][ty * 16];
            float4 a1 = *(const float4*)&As[buf][kk][ty * 16 + 4];
            float4 a2 = *(const float4*)&As[buf][kk][ty * 16 + 8];
            float4 a3 = *(const float4*)&As[buf][kk][ty * 16 + 12];
            float4 b0 = *(const float4*)&Bs[buf][kk][tx * 8];
            float4 b1 = *(const float4*)&Bs[buf][kk][tx * 8 + 4];

            // a-pairs: reinterpret consecutive float pairs as packed f32x2
            unsigned long long ap[8];
            ap[0] = ((unsigned long long*)&a0)[0];
            ap[1] = ((unsigned long long*)&a0)[1];
            ap[2] = ((unsigned long long*)&a1)[0];
            ap[3] = ((unsigned long long*)&a1)[1];
            ap[4] = ((unsigned long long*)&a2)[0];
            ap[5] = ((unsigned long long*)&a2)[1];
            ap[6] = ((unsigned long long*)&a3)[0];
            ap[7] = ((unsigned long long*)&a3)[1];
            // b duplicated into both halves
            unsigned long long bp[8];
            bp[0] = pack2(b0.x, b0.x); bp[1] = pack2(b0.y, b0.y);
            bp[2] = pack2(b0.z, b0.z); bp[3] = pack2(b0.w, b0.w);
            bp[4] = pack2(b1.x, b1.x); bp[5] = pack2(b1.y, b1.y);
            bp[6] = pack2(b1.z, b1.z); bp[7] = pack2(b1.w, b1.w);

            #pragma unroll
            for (int i = 0; i < 8; i++)
                #pragma unroll
                for (int j = 0; j < 8; j++)
                    ffma2(acc[i][j], ap[i], bp[j]);
        }

        if (more) {
            const int nb = buf ^ 1;
            #pragma unroll
            for (int f = 0; f < 4; f++) {
                As[nb][f * 4 + 0][tid] = aReg[f].x;
                As[nb][f * 4 + 1][tid] = aReg[f].y;
                As[nb][f * 4 + 2][tid] = aReg[f].z;
                As[nb][f * 4 + 3][tid] = aReg[f].w;
                *(float4*)&Bs[nb][bK][bC + f * 4] = bReg[f];
            }
            __syncthreads();
            buf = nb;
        }
    }

    // epilogue: acc[i][j] holds rows (ty*16 + 2i, +2i+1), col tx*8 + j
    #pragma unroll
    for (int i = 0; i < 8; i++) {
        const int r0 = rowBase + ty * 16 + 2 * i;
        float lo[8], hi[8];
        #pragma unroll
        for (int j = 0; j < 8; j++) {
            float2 v = *(float2*)&acc[i][j];
            lo[j] = v.x; hi[j] = v.y;
        }
        #pragma unroll
        for (int half = 0; half < 2; half++) {
            const int col = colBase + tx * 8 + half * 4;
            if (col < N) {
                *(float4*)(C + (size_t)r0 * N + col) =
                    make_float4(lo[half*4+0], lo[half*4+1], lo[half*4+2], lo[half*4+3]);
                *(float4*)(C + (size_t)(r0 + 1) * N + col) =
                    make_float4(hi[half*4+0], hi[half*4+1], hi[half*4+2], hi[half*4+3]);
            }
        }
    }
}

// ---------------- causal depthwise conv1d (k=4) + bias + SiLU --------------
__global__ __launch_bounds__(256) void conv_kernel(
    const float* __restrict__ conv_w, const float* __restrict__ conv_b)
{
    const int l = blockIdx.x;
    const int b = blockIdx.y;
    const size_t orow = (size_t)(b * SEQLEN + l);

    for (int c = threadIdx.x; c < CONVDIM; c += 256) {
        float s = conv_b[c];
        #pragma unroll
        for (int k = 0; k < DCONV; k++) {
            const int ls = l - (DCONV - 1) + k;
            if (ls >= 0)
                s = fmaf(g_zxbcdt[((size_t)(b * SEQLEN + ls)) * NPROJ + DINNER + c],
                         conv_w[c * DCONV + k], s);
        }
        const float sil = s / (1.f + __expf(-s));
        g_xbc[orow * CONVDIM + c] = sil;
    }
}

// ---------------- dt = softplus(dt_raw + dt_bias) --------------------------
__global__ __launch_bounds__(256) void dt_kernel(const float* __restrict__ dt_bias)
{
    const int i = blockIdx.x * 256 + threadIdx.x;   // over MROWS*NH
    if (i >= MROWS * NH) return;
    const int h = i & (NH - 1);
    const int row = i >> 5;
    const float v = g_zxbcdt[(size_t)row * NPROJ + (DINNER + CONVDIM) + h] + dt_bias[h];
    g_dt[i] = (v > 20.f) ? v : log1pf(expf(v));
}

// ---------------- sequential selective scan --------------------------------
// Block = one (b, h). 512 threads: p = tid>>3 (0..63), nc = tid&7 (8 states
// each). 3-shuffle reduction over the 8 n-chunks per p.
// Distance-2 register prefetch of B/C/x/dt to hide L2 latency.
__global__ __launch_bounds__(512) void scan_kernel(
    const float* __restrict__ A_log, const float* __restrict__ Dv)
{
    const int bh = blockIdx.x;
    const int b = bh >> 5, h = bh & (NH - 1);
    const int tid = threadIdx.x;
    const int p  = tid >> 3;
    const int nc = tid & 7;
    const int n0 = nc * 8;

    const float Aneg = -__expf(A_log[h]);
    const float Dh   = Dv[h];

    const float* xptr = g_xbc + (size_t)b * SEQLEN * CONVDIM + h * HEADDIM + p;
    const float* Bptr = g_xbc + (size_t)b * SEQLEN * CONVDIM + DINNER + n0;
    const float* Cptr = g_xbc + (size_t)b * SEQLEN * CONVDIM + DINNER + DSTATE + n0;
    const float* dptr = g_dt  + (size_t)b * SEQLEN * NH + h;
    float*       yptr = g_y   + (size_t)b * SEQLEN * DINNER + h * HEADDIM + p;

    float hs[8];
    #pragma unroll
    for (int i = 0; i < 8; i++) hs[i] = 0.f;

    float4 Bf0[2], Cf0[2], Bf1[2], Cf1[2];
    float xf0, df0, xf1, df1;

#define SCAN_LOAD(t, Bf, Cf, xf, df) do {                                   \
        const float4* bp_ = (const float4*)(Bptr + (size_t)(t) * CONVDIM);  \
        Bf[0] = bp_[0]; Bf[1] = bp_[1];                                     \
        const float4* cp_ = (const float4*)(Cptr + (size_t)(t) * CONVDIM);  \
        Cf[0] = cp_[0]; Cf[1] = cp_[1];                                     \
        xf = xptr[(size_t)(t) * CONVDIM];                                   \
        df = dptr[(size_t)(t) * NH];                                        \
    } while (0)

#define SCAN_STEP(t, Bf, Cf, xf, df) do {                                   \
        const float dA   = __expf((df) * Aneg);                             \
        const float coef = (df) * (xf);                                     \
        float acc = 0.f;                                                    \
        _Pragma("unroll")                                                   \
        for (int q = 0; q < 2; q++) {                                       \
            const float4 bq = Bf[q], cq = Cf[q];                            \
            hs[q*4+0] = fmaf(hs[q*4+0], dA, coef * bq.x);                   \
            acc = fmaf(hs[q*4+0], cq.x, acc);                               \
            hs[q*4+1] = fmaf(hs[q*4+1], dA, coef * bq.y);                   \
            acc = fmaf(hs[q*4+1], cq.y, acc);                               \
            hs[q*4+2] = fmaf(hs[q*4+2], dA, coef * bq.z);                   \
            acc = fmaf(hs[q*4+2], cq.z, acc);                               \
            hs[q*4+3] = fmaf(hs[q*4+3], dA, coef * bq.w);                   \
            acc = fmaf(hs[q*4+3], cq.w, acc);                               \
        }                                                                   \
        acc += __shfl_xor_sync(0xffffffffu, acc, 1);                        \
        acc += __shfl_xor_sync(0xffffffffu, acc, 2);                        \
        acc += __shfl_xor_sync(0xffffffffu, acc, 4);                        \
        if (nc == 0) yptr[(size_t)(t) * DINNER] = acc + Dh * (xf);          \
    } while (0)

    SCAN_LOAD(0, Bf0, Cf0, xf0, df0);
    SCAN_LOAD(1, Bf1, Cf1, xf1, df1);

    for (int t = 0; t < SEQLEN; t += 2) {
        SCAN_STEP(t, Bf0, Cf0, xf0, df0);
        if (t + 2 < SEQLEN) SCAN_LOAD(t + 2, Bf0, Cf0, xf0, df0);
        SCAN_STEP(t + 1, Bf1, Cf1, xf1, df1);
        if (t + 3 < SEQLEN) SCAN_LOAD(t + 3, Bf1, Cf1, xf1, df1);
    }
#undef SCAN_LOAD
#undef SCAN_STEP
}

// ---------------- y = rmsnorm(y * silu(z)) * norm_w (in place) -------------
__global__ __launch_bounds__(256) void gatenorm_kernel(const float* __restrict__ norm_w)
{
    const int row = blockIdx.x;
    const float* zrow = g_zxbcdt + (size_t)row * NPROJ;   // z = first DINNER cols
    float* yrow = g_y + (size_t)row * DINNER;

    float v[8];
    float ss = 0.f;
    #pragma unroll
    for (int j = 0; j < 8; j++) {
        const int i = threadIdx.x + j * 256;
        const float z = zrow[i];
        const float g = yrow[i] * (z / (1.f + __expf(-z)));
        v[j] = g;
        ss = fmaf(g, g, ss);
    }
    #pragma unroll
    for (int o = 16; o; o >>= 1) ss += __shfl_xor_sync(0xffffffffu, ss, o);

    __shared__ float red[8];
    __shared__ float s_rstd;
    if ((threadIdx.x & 31) == 0) red[threadIdx.x >> 5] = ss;
    __syncthreads();
    if (threadIdx.x == 0) {
        float t = 0.f;
        #pragma unroll
        for (int w = 0; w < 8; w++) t += red[w];
        s_rstd = rsqrtf(t / (float)DINNER + 1e-5f);
    }
    __syncthreads();
    const float rstd = s_rstd;

    #pragma unroll
    for (int j = 0; j < 8; j++) {
        const int i = threadIdx.x + j * 256;
        yrow[i] = v[j] * rstd * norm_w[i];
    }
}

// ---------------- launch ----------------------------------------------------
extern "C" void kernel_launch(void* const* d_in, const int* in_sizes, int n_in,
                              void* d_out, int out_size)
{
    const float* x       = (const float*)d_in[0];
    const float* W_in    = (const float*)d_in[1];
    const float* conv_w  = (const float*)d_in[2];
    const float* conv_b  = (const float*)d_in[3];
    const float* dt_bias = (const float*)d_in[4];
    const float* A_log   = (const float*)d_in[5];
    const float* Dvec    = (const float*)d_in[6];
    const float* norm_w  = (const float*)d_in[7];
    const float* W_out   = (const float*)d_in[8];
    float* out = (float*)d_out;

    void *p_zx, *p_y;
    cudaGetSymbolAddress(&p_zx, g_zxbcdt);
    cudaGetSymbolAddress(&p_y,  g_y);
    float* zx = (float*)p_zx;
    float* y  = (float*)p_y;

    // 1) in-projection: zxbcdt = x @ W_in   [8192,1024]@[1024,4256]
    {
        dim3 grid((NPROJ + BN - 1) / BN, MROWS / BM);
        gemm2_kernel<<<grid, 128>>>(x, W_in, zx, MROWS, NPROJ, DMODEL);
    }
    // 2) conv + SiLU
    conv_kernel<<<dim3(SEQLEN, BATCH), 256>>>(conv_w, conv_b);
    // 3) dt softplus
    dt_kernel<<<(MROWS * NH + 255) / 256, 256>>>(dt_bias);
    // 4) selective scan
    scan_kernel<<<BATCH * NH, 512>>>(A_log, Dvec);
    // 5) gate + rmsnorm (in place on g_y)
    gatenorm_kernel<<<MROWS, 256>>>(norm_w);
    // 6) out-projection: out = y @ W_out   [8192,2048]@[2048,1024]
    {
        dim3 grid(DMODEL / BN, MROWS / BM);
        gemm2_kernel<<<grid, 128>>>(y, W_out, out, MROWS, DMODEL, DINNER);
    }
}